// round 3
// baseline (speedup 1.0000x reference)
#include <cuda_runtime.h>
#include <cuda_fp16.h>
#include <cstdint>
#include <cstddef>

// ---------------------------------------------------------------------------
// Problem dims
// ---------------------------------------------------------------------------
#define T_DIM 256
#define B_DIM 128
#define I_DIM 512
#define H_DIM 2048
#define O_DIM 512
#define M_DIM (T_DIM * B_DIM)   // 32768 rows of proj

// ---------------------------------------------------------------------------
// Scratch (device globals)
// ---------------------------------------------------------------------------
__device__ __half g_Xh[(size_t)M_DIM * I_DIM];        // 33.5 MB fp16
__device__ __half g_Wh[(size_t)H_DIM * I_DIM];        // 2 MB fp16
__device__ __half g_proj[(size_t)M_DIM * H_DIM];      // 134 MB fp16
__device__ float  g_hfin[(size_t)B_DIM * H_DIM];      // 1 MB
__device__ float  g_part[8 * (size_t)B_DIM * O_DIM];  // 2 MB

// ---------------------------------------------------------------------------
// PTX helpers (Ampere-compatible: cp.async / ldmatrix / mma.sync)
// ---------------------------------------------------------------------------
__device__ __forceinline__ uint32_t smem_u32(const void* p) {
    uint32_t a;
    asm("{ .reg .u64 t; cvta.to.shared.u64 t, %1; cvt.u32.u64 %0, t; }" : "=r"(a) : "l"(p));
    return a;
}
__device__ __forceinline__ void cp16(uint32_t dst, const void* src) {
    asm volatile("cp.async.cg.shared.global [%0], [%1], 16;" :: "r"(dst), "l"(src));
}
#define CP_COMMIT() asm volatile("cp.async.commit_group;" ::: "memory")
#define CP_WAIT(n)  asm volatile("cp.async.wait_group %0;" :: "n"(n) : "memory")

__device__ __forceinline__ void ldm_x4(uint32_t* r, uint32_t addr) {
    asm volatile("ldmatrix.sync.aligned.m8n8.x4.shared.b16 {%0,%1,%2,%3}, [%4];"
                 : "=r"(r[0]), "=r"(r[1]), "=r"(r[2]), "=r"(r[3]) : "r"(addr));
}
__device__ __forceinline__ void mma16816(float* c, const uint32_t* a, uint32_t b0, uint32_t b1) {
    asm volatile(
        "mma.sync.aligned.m16n8k16.row.col.f32.f16.f16.f32 "
        "{%0,%1,%2,%3}, {%4,%5,%6,%7}, {%8,%9}, {%0,%1,%2,%3};"
        : "+f"(c[0]), "+f"(c[1]), "+f"(c[2]), "+f"(c[3])
        : "r"(a[0]), "r"(a[1]), "r"(a[2]), "r"(a[3]), "r"(b0), "r"(b1));
}

// ---------------------------------------------------------------------------
// 1) fp32 -> fp16 conversion (X split into two launches for ncu positioning)
// ---------------------------------------------------------------------------
__global__ void k_cvt_x(const float4* __restrict__ src, size_t base) {
    size_t i = base + (size_t)blockIdx.x * blockDim.x + threadIdx.x;
    float4 v = src[i];
    __half2 h0 = __floats2half2_rn(v.x, v.y);
    __half2 h1 = __floats2half2_rn(v.z, v.w);
    ((__half2*)g_Xh)[i * 2]     = h0;
    ((__half2*)g_Xh)[i * 2 + 1] = h1;
}
__global__ void k_cvt_w(const float4* __restrict__ src) {
    size_t i = (size_t)blockIdx.x * blockDim.x + threadIdx.x;  // 262,144
    float4 v = src[i];
    __half2 h0 = __floats2half2_rn(v.x, v.y);
    __half2 h1 = __floats2half2_rn(v.z, v.w);
    ((__half2*)g_Wh)[i * 2]     = h0;
    ((__half2*)g_Wh)[i * 2 + 1] = h1;
}

// ---------------------------------------------------------------------------
// 2) proj = X @ W_IH^T  (fp16 in, fp32 accum, fp16 out)
//    128x128x64 CTA tile, 3-stage cp.async pipeline, 8 warps (4x2), warp 32x64
// ---------------------------------------------------------------------------
#define STAGE_BYTES 32768          // A 16KB + B 16KB
#define NSTAGE 3

__global__ void __launch_bounds__(256) k_gemm() {
    extern __shared__ __align__(1024) uint8_t dynsmem[];
    const uint32_t sbase = smem_u32(dynsmem);

    const int tid  = threadIdx.x;
    const int wid  = tid >> 5;
    const int lane = tid & 31;
    const int wm   = wid & 3;          // 0..3  (M direction)
    const int wn   = wid >> 2;         // 0..1  (N direction)
    const int n0   = blockIdx.x * 128; // over H
    const int m0   = blockIdx.y * 128; // over T*B

    const uint8_t* Ag = (const uint8_t*)(g_Xh + (size_t)m0 * I_DIM);
    const uint8_t* Bg = (const uint8_t*)(g_Wh + (size_t)n0 * I_DIM);

    float acc[2][8][4];
    #pragma unroll
    for (int i = 0; i < 2; ++i)
        #pragma unroll
        for (int j = 0; j < 8; ++j)
            #pragma unroll
            for (int q = 0; q < 4; ++q) acc[i][j][q] = 0.f;

    auto load_stage = [&](int kt, int st) {
        const uint32_t sA = sbase + st * STAGE_BYTES;
        const uint32_t sB = sA + 16384;
        const int koff = kt * 128;   // bytes along K
        #pragma unroll
        for (int i = 0; i < 4; ++i) {
            int c = tid + i * 256;           // 0..1023
            int row = c >> 3, j = c & 7;
            uint32_t sw = (uint32_t)(row * 128 + ((j ^ (row & 7)) * 16));
            cp16(sA + sw, Ag + (size_t)row * 1024 + koff + j * 16);
            cp16(sB + sw, Bg + (size_t)row * 1024 + koff + j * 16);
        }
    };

    load_stage(0, 0); CP_COMMIT();
    load_stage(1, 1); CP_COMMIT();

    for (int kt = 0; kt < 8; ++kt) {
        if (kt + 2 < 8) load_stage(kt + 2, (kt + 2) % NSTAGE);
        CP_COMMIT();
        CP_WAIT(2);
        __syncthreads();

        const int st = kt % NSTAGE;
        const uint32_t sA = sbase + st * STAGE_BYTES;
        const uint32_t sB = sA + 16384;

        #pragma unroll
        for (int ks = 0; ks < 4; ++ks) {
            const int j = ks * 2 + (lane >> 4);
            uint32_t a[2][4];
            #pragma unroll
            for (int im = 0; im < 2; ++im) {
                int r = wm * 32 + im * 16 + (lane & 15);
                ldm_x4(a[im], sA + r * 128 + ((j ^ (r & 7)) * 16));
            }
            uint32_t b[4][4];
            #pragma unroll
            for (int in = 0; in < 4; ++in) {
                int r = wn * 64 + in * 16 + (lane & 15);
                ldm_x4(b[in], sB + r * 128 + ((j ^ (r & 7)) * 16));
            }
            #pragma unroll
            for (int im = 0; im < 2; ++im)
                #pragma unroll
                for (int in = 0; in < 4; ++in) {
                    mma16816(acc[im][2 * in + 0], a[im], b[in][0], b[in][2]);
                    mma16816(acc[im][2 * in + 1], a[im], b[in][1], b[in][3]);
                }
        }
        __syncthreads();
    }

    // epilogue: fp32 acc -> fp16 proj
    #pragma unroll
    for (int im = 0; im < 2; ++im) {
        const int rbase = m0 + wm * 32 + im * 16 + (lane >> 2);
        #pragma unroll
        for (int jn = 0; jn < 8; ++jn) {
            const int col = n0 + wn * 64 + jn * 8 + (lane & 3) * 2;
            __half2 v0 = __floats2half2_rn(acc[im][jn][0], acc[im][jn][1]);
            __half2 v1 = __floats2half2_rn(acc[im][jn][2], acc[im][jn][3]);
            *(__half2*)(g_proj + (size_t)rbase * H_DIM + col)       = v0;
            *(__half2*)(g_proj + (size_t)(rbase + 8) * H_DIM + col) = v1;
        }
    }
}

// ---------------------------------------------------------------------------
// 3) scan over t:  h = |proj_t + HH*h|
//    4 h-lanes/thread (8B loads), 65536 threads, unroll 8 -> high MLP
// ---------------------------------------------------------------------------
__global__ void __launch_bounds__(256) k_scan(const float* __restrict__ HH) {
    const int idx = blockIdx.x * blockDim.x + threadIdx.x;  // 65536 = B*H/4
    const int h4 = idx & (H_DIM / 4 - 1);    // which group of 4 h
    const int b  = idx >> 9;                  // H/4 = 512
    const int h  = h4 * 4;
    const float hh0 = HH[h], hh1 = HH[h + 1], hh2 = HH[h + 2], hh3 = HH[h + 3];
    const uint2* p = (const uint2*)g_proj + ((size_t)b * H_DIM + h) / 4;
    const size_t tstride = (size_t)B_DIM * H_DIM / 4;   // in uint2
    float a0 = 0.f, a1 = 0.f, a2 = 0.f, a3 = 0.f;
    #pragma unroll 8
    for (int t = 0; t < T_DIM; ++t) {
        uint2 u = p[(size_t)t * tstride];
        __half2 lo = *(__half2*)&u.x;
        __half2 hi = *(__half2*)&u.y;
        float2 f0 = __half22float2(lo);
        float2 f1 = __half22float2(hi);
        a0 = fabsf(f0.x + hh0 * a0);
        a1 = fabsf(f0.y + hh1 * a1);
        a2 = fabsf(f1.x + hh2 * a2);
        a3 = fabsf(f1.y + hh3 * a3);
    }
    float4* out = (float4*)(g_hfin + (size_t)b * H_DIM + h);
    *out = make_float4(a0, a1, a2, a3);
}

// ---------------------------------------------------------------------------
// 4) Y = h @ W_HO^T + b : 8-way K-split partial GEMM + reduction
// ---------------------------------------------------------------------------
__global__ void k_ogemm(const float* __restrict__ W) {
    __shared__ float hs[32][65];
    __shared__ float ws[64][65];
    const int tid = threadIdx.x;
    const int tx = tid & 63;
    const int ty = tid >> 6;
    const int o0 = blockIdx.x * 64;
    const int b0 = blockIdx.y * 32;
    const int kb = blockIdx.z * 256;

    float acc[8];
    #pragma unroll
    for (int j = 0; j < 8; ++j) acc[j] = 0.f;

    for (int kc = 0; kc < 4; ++kc) {
        const int k0 = kb + kc * 64;
        #pragma unroll
        for (int l = 0; l < 8; ++l) {
            int i = tid + l * 256;
            int r = i >> 6, c = i & 63;
            hs[r][c] = g_hfin[(size_t)(b0 + r) * H_DIM + k0 + c];
        }
        #pragma unroll
        for (int l = 0; l < 16; ++l) {
            int i = tid + l * 256;
            int r = i >> 6, c = i & 63;
            ws[r][c] = W[(size_t)(o0 + r) * H_DIM + k0 + c];
        }
        __syncthreads();
        #pragma unroll
        for (int k = 0; k < 64; ++k) {
            float wv = ws[tx][k];
            #pragma unroll
            for (int j = 0; j < 8; ++j)
                acc[j] = fmaf(hs[ty + 4 * j][k], wv, acc[j]);
        }
        __syncthreads();
    }

    float* part = g_part + (size_t)blockIdx.z * (B_DIM * O_DIM);
    #pragma unroll
    for (int j = 0; j < 8; ++j)
        part[(size_t)(b0 + ty + 4 * j) * O_DIM + o0 + tx] = acc[j];
}

__global__ void k_reduce(const float* __restrict__ bias, float* __restrict__ Y) {
    const int i = blockIdx.x * blockDim.x + threadIdx.x;  // 65536
    float s = bias[i & (O_DIM - 1)];
    #pragma unroll
    for (int p = 0; p < 8; ++p) s += g_part[(size_t)p * (B_DIM * O_DIM) + i];
    Y[i] = s;
}

// ---------------------------------------------------------------------------
// launch
// ---------------------------------------------------------------------------
extern "C" void kernel_launch(void* const* d_in, const int* in_sizes, int n_in,
                              void* d_out, int out_size) {
    const float* X    = (const float*)d_in[0];
    const float* W_IH = (const float*)d_in[1];
    const float* HH   = (const float*)d_in[2];
    const float* W_HO = (const float*)d_in[3];
    const float* b_HO = (const float*)d_in[4];
    float* Y = (float*)d_out;

    cudaFuncSetAttribute(k_gemm, cudaFuncAttributeMaxDynamicSharedMemorySize,
                         NSTAGE * STAGE_BYTES);

    // launches #1..#3 (cvt) so that k_gemm is launch #4 for the ncu window
    k_cvt_x<<<8192, 256>>>((const float4*)X, 0);
    k_cvt_x<<<8192, 256>>>((const float4*)X, (size_t)8192 * 256);
    k_cvt_w<<<1024, 256>>>((const float4*)W_IH);
    k_gemm<<<dim3(16, 256), 256, NSTAGE * STAGE_BYTES>>>();
    k_scan<<<256, 256>>>(HH);
    k_ogemm<<<dim3(8, 4, 8), 256>>>(W_HO);
    k_reduce<<<256, 256>>>(b_HO, Y);
}

// round 4
// speedup vs baseline: 1.0336x; 1.0336x over previous
#include <cuda_runtime.h>
#include <cuda_fp16.h>
#include <cstdint>
#include <cstddef>

// ---------------------------------------------------------------------------
// Problem dims
// ---------------------------------------------------------------------------
#define T_DIM 256
#define B_DIM 128
#define I_DIM 512
#define H_DIM 2048
#define O_DIM 512
#define M_DIM (T_DIM * B_DIM)   // 32768 rows of proj

// ---------------------------------------------------------------------------
// Scratch (device globals)
// ---------------------------------------------------------------------------
__device__ __half g_Xh[(size_t)M_DIM * I_DIM];        // 33.5 MB fp16
__device__ __half g_Wh[(size_t)H_DIM * I_DIM];        // 2 MB fp16
__device__ __half g_proj[(size_t)M_DIM * H_DIM];      // 134 MB fp16
__device__ float  g_hfin[(size_t)B_DIM * H_DIM];      // 1 MB
__device__ float  g_part[8 * (size_t)B_DIM * O_DIM];  // 2 MB

// ---------------------------------------------------------------------------
// PTX helpers (Ampere-compatible: cp.async / ldmatrix / mma.sync)
// ---------------------------------------------------------------------------
__device__ __forceinline__ uint32_t smem_u32(const void* p) {
    uint32_t a;
    asm("{ .reg .u64 t; cvta.to.shared.u64 t, %1; cvt.u32.u64 %0, t; }" : "=r"(a) : "l"(p));
    return a;
}
__device__ __forceinline__ void cp16(uint32_t dst, const void* src) {
    asm volatile("cp.async.cg.shared.global [%0], [%1], 16;" :: "r"(dst), "l"(src));
}
#define CP_COMMIT() asm volatile("cp.async.commit_group;" ::: "memory")
#define CP_WAIT(n)  asm volatile("cp.async.wait_group %0;" :: "n"(n) : "memory")

__device__ __forceinline__ void ldm_x4(uint32_t* r, uint32_t addr) {
    asm volatile("ldmatrix.sync.aligned.m8n8.x4.shared.b16 {%0,%1,%2,%3}, [%4];"
                 : "=r"(r[0]), "=r"(r[1]), "=r"(r[2]), "=r"(r[3]) : "r"(addr));
}
__device__ __forceinline__ void mma16816(float* c, const uint32_t* a, uint32_t b0, uint32_t b1) {
    asm volatile(
        "mma.sync.aligned.m16n8k16.row.col.f32.f16.f16.f32 "
        "{%0,%1,%2,%3}, {%4,%5,%6,%7}, {%8,%9}, {%0,%1,%2,%3};"
        : "+f"(c[0]), "+f"(c[1]), "+f"(c[2]), "+f"(c[3])
        : "r"(a[0]), "r"(a[1]), "r"(a[2]), "r"(a[3]), "r"(b0), "r"(b1));
}

// ---------------------------------------------------------------------------
// 1) fp32 -> fp16 conversion
// ---------------------------------------------------------------------------
__global__ void k_cvt_x(const float4* __restrict__ src, size_t base) {
    size_t i = base + (size_t)blockIdx.x * blockDim.x + threadIdx.x;
    float4 v = src[i];
    __half2 h0 = __floats2half2_rn(v.x, v.y);
    __half2 h1 = __floats2half2_rn(v.z, v.w);
    ((__half2*)g_Xh)[i * 2]     = h0;
    ((__half2*)g_Xh)[i * 2 + 1] = h1;
}
__global__ void k_cvt_w(const float4* __restrict__ src) {
    size_t i = (size_t)blockIdx.x * blockDim.x + threadIdx.x;  // 262,144
    float4 v = src[i];
    __half2 h0 = __floats2half2_rn(v.x, v.y);
    __half2 h1 = __floats2half2_rn(v.z, v.w);
    ((__half2*)g_Wh)[i * 2]     = h0;
    ((__half2*)g_Wh)[i * 2 + 1] = h1;
}

// ---------------------------------------------------------------------------
// 2) proj = X @ W_IH^T  (fp16 in, fp32 accum, fp16 out)
//    128x128x64 CTA tile, 3-stage cp.async pipeline, ONE sync per k-tile,
//    register double-buffered fragments. 8 warps (4x2), warp tile 32x64.
// ---------------------------------------------------------------------------
#define STAGE_BYTES 32768          // A 16KB + B 16KB
#define NSTAGE 3

__global__ void __launch_bounds__(256, 2) k_gemm() {
    extern __shared__ __align__(1024) uint8_t dynsmem[];
    const uint32_t sbase = smem_u32(dynsmem);

    const int tid  = threadIdx.x;
    const int wid  = tid >> 5;
    const int lane = tid & 31;
    const int wm   = wid & 3;          // 0..3  (M direction)
    const int wn   = wid >> 2;         // 0..1  (N direction)
    const int n0   = blockIdx.x * 128; // over H
    const int m0   = blockIdx.y * 128; // over T*B

    const uint8_t* Ag = (const uint8_t*)(g_Xh + (size_t)m0 * I_DIM);
    const uint8_t* Bg = (const uint8_t*)(g_Wh + (size_t)n0 * I_DIM);

    float acc[2][8][4];
    #pragma unroll
    for (int i = 0; i < 2; ++i)
        #pragma unroll
        for (int j = 0; j < 8; ++j)
            #pragma unroll
            for (int q = 0; q < 4; ++q) acc[i][j][q] = 0.f;

    auto load_stage = [&](int kt, int st) {
        const uint32_t sA = sbase + st * STAGE_BYTES;
        const uint32_t sB = sA + 16384;
        const int koff = kt * 128;   // bytes along K
        #pragma unroll
        for (int i = 0; i < 4; ++i) {
            int c = tid + i * 256;           // 0..1023
            int row = c >> 3, j = c & 7;
            uint32_t sw = (uint32_t)(row * 128 + ((j ^ (row & 7)) * 16));
            cp16(sA + sw, Ag + (size_t)row * 1024 + koff + j * 16);
            cp16(sB + sw, Bg + (size_t)row * 1024 + koff + j * 16);
        }
    };

    // fragment double buffers
    uint32_t a_frag[2][2][4];
    uint32_t b_frag[2][4][4];
    const int rA0 = wm * 32 + (lane & 15);
    const int rB0 = wn * 64 + (lane & 15);
    const int jlo = (lane >> 4);

    auto ld_frags = [&](int buf, uint32_t sA, uint32_t sB, int ks) {
        const int j = ks * 2 + jlo;
        #pragma unroll
        for (int im = 0; im < 2; ++im) {
            int r = rA0 + im * 16;
            ldm_x4(a_frag[buf][im], sA + r * 128 + ((j ^ (r & 7)) * 16));
        }
        #pragma unroll
        for (int in = 0; in < 4; ++in) {
            int r = rB0 + in * 16;
            ldm_x4(b_frag[buf][in], sB + r * 128 + ((j ^ (r & 7)) * 16));
        }
    };

    // prologue
    load_stage(0, 0); CP_COMMIT();
    load_stage(1, 1); CP_COMMIT();
    CP_WAIT(1);
    __syncthreads();
    ld_frags(0, sbase, sbase + 16384, 0);

    for (int kt = 0; kt < 8; ++kt) {
        const uint32_t sA  = sbase + (kt % NSTAGE) * STAGE_BYTES;
        const uint32_t sB  = sA + 16384;
        const uint32_t sAn = sbase + ((kt + 1) % NSTAGE) * STAGE_BYTES;
        const uint32_t sBn = sAn + 16384;

        #pragma unroll
        for (int ks = 0; ks < 4; ++ks) {
            const int cur = ks & 1, nxt = cur ^ 1;
            if (ks == 0) {
                if (kt + 2 < 8) load_stage(kt + 2, (kt + 2) % NSTAGE);
                CP_COMMIT();
            }
            if (ks == 3) {
                CP_WAIT(1);
                __syncthreads();
                ld_frags(nxt, sAn, sBn, 0);     // first frags of next stage
            } else {
                ld_frags(nxt, sA, sB, ks + 1);
            }
            #pragma unroll
            for (int im = 0; im < 2; ++im)
                #pragma unroll
                for (int in = 0; in < 4; ++in) {
                    mma16816(acc[im][2 * in + 0], a_frag[cur][im],
                             b_frag[cur][in][0], b_frag[cur][in][2]);
                    mma16816(acc[im][2 * in + 1], a_frag[cur][im],
                             b_frag[cur][in][1], b_frag[cur][in][3]);
                }
        }
    }

    // epilogue: fp32 acc -> fp16 proj
    #pragma unroll
    for (int im = 0; im < 2; ++im) {
        const int rbase = m0 + wm * 32 + im * 16 + (lane >> 2);
        #pragma unroll
        for (int jn = 0; jn < 8; ++jn) {
            const int col = n0 + wn * 64 + jn * 8 + (lane & 3) * 2;
            __half2 v0 = __floats2half2_rn(acc[im][jn][0], acc[im][jn][1]);
            __half2 v1 = __floats2half2_rn(acc[im][jn][2], acc[im][jn][3]);
            *(__half2*)(g_proj + (size_t)rbase * H_DIM + col)       = v0;
            *(__half2*)(g_proj + (size_t)(rbase + 8) * H_DIM + col) = v1;
        }
    }
}

// ---------------------------------------------------------------------------
// 3) scan over t:  h = |proj_t + HH*h|
// ---------------------------------------------------------------------------
__global__ void __launch_bounds__(256) k_scan(const float* __restrict__ HH) {
    const int idx = blockIdx.x * blockDim.x + threadIdx.x;  // 65536 = B*H/4
    const int h4 = idx & (H_DIM / 4 - 1);
    const int b  = idx >> 9;
    const int h  = h4 * 4;
    const float hh0 = HH[h], hh1 = HH[h + 1], hh2 = HH[h + 2], hh3 = HH[h + 3];
    const uint2* p = (const uint2*)g_proj + ((size_t)b * H_DIM + h) / 4;
    const size_t tstride = (size_t)B_DIM * H_DIM / 4;   // in uint2
    float a0 = 0.f, a1 = 0.f, a2 = 0.f, a3 = 0.f;
    #pragma unroll 8
    for (int t = 0; t < T_DIM; ++t) {
        uint2 u = p[(size_t)t * tstride];
        __half2 lo = *(__half2*)&u.x;
        __half2 hi = *(__half2*)&u.y;
        float2 f0 = __half22float2(lo);
        float2 f1 = __half22float2(hi);
        a0 = fabsf(f0.x + hh0 * a0);
        a1 = fabsf(f0.y + hh1 * a1);
        a2 = fabsf(f1.x + hh2 * a2);
        a3 = fabsf(f1.y + hh3 * a3);
    }
    float4* out = (float4*)(g_hfin + (size_t)b * H_DIM + h);
    *out = make_float4(a0, a1, a2, a3);
}

// ---------------------------------------------------------------------------
// 4) Y = h @ W_HO^T + b : 8-way K-split partial GEMM + reduction
// ---------------------------------------------------------------------------
__global__ void k_ogemm(const float* __restrict__ W) {
    __shared__ float hs[32][65];
    __shared__ float ws[64][65];
    const int tid = threadIdx.x;
    const int tx = tid & 63;
    const int ty = tid >> 6;
    const int o0 = blockIdx.x * 64;
    const int b0 = blockIdx.y * 32;
    const int kb = blockIdx.z * 256;

    float acc[8];
    #pragma unroll
    for (int j = 0; j < 8; ++j) acc[j] = 0.f;

    for (int kc = 0; kc < 4; ++kc) {
        const int k0 = kb + kc * 64;
        #pragma unroll
        for (int l = 0; l < 8; ++l) {
            int i = tid + l * 256;
            int r = i >> 6, c = i & 63;
            hs[r][c] = g_hfin[(size_t)(b0 + r) * H_DIM + k0 + c];
        }
        #pragma unroll
        for (int l = 0; l < 16; ++l) {
            int i = tid + l * 256;
            int r = i >> 6, c = i & 63;
            ws[r][c] = W[(size_t)(o0 + r) * H_DIM + k0 + c];
        }
        __syncthreads();
        #pragma unroll
        for (int k = 0; k < 64; ++k) {
            float wv = ws[tx][k];
            #pragma unroll
            for (int j = 0; j < 8; ++j)
                acc[j] = fmaf(hs[ty + 4 * j][k], wv, acc[j]);
        }
        __syncthreads();
    }

    float* part = g_part + (size_t)blockIdx.z * (B_DIM * O_DIM);
    #pragma unroll
    for (int j = 0; j < 8; ++j)
        part[(size_t)(b0 + ty + 4 * j) * O_DIM + o0 + tx] = acc[j];
}

__global__ void k_reduce(const float* __restrict__ bias, float* __restrict__ Y) {
    const int i = blockIdx.x * blockDim.x + threadIdx.x;  // 65536
    float s = bias[i & (O_DIM - 1)];
    #pragma unroll
    for (int p = 0; p < 8; ++p) s += g_part[(size_t)p * (B_DIM * O_DIM) + i];
    Y[i] = s;
}

// ---------------------------------------------------------------------------
// launch
// ---------------------------------------------------------------------------
extern "C" void kernel_launch(void* const* d_in, const int* in_sizes, int n_in,
                              void* d_out, int out_size) {
    const float* X    = (const float*)d_in[0];
    const float* W_IH = (const float*)d_in[1];
    const float* HH   = (const float*)d_in[2];
    const float* W_HO = (const float*)d_in[3];
    const float* b_HO = (const float*)d_in[4];
    float* Y = (float*)d_out;

    cudaFuncSetAttribute(k_gemm, cudaFuncAttributeMaxDynamicSharedMemorySize,
                         NSTAGE * STAGE_BYTES);

    // keep k_gemm at launch #4 (matches the ncu capture slot seen in R3)
    k_cvt_x<<<8192, 256>>>((const float4*)X, 0);
    k_cvt_x<<<8192, 256>>>((const float4*)X, (size_t)8192 * 256);
    k_cvt_w<<<1024, 256>>>((const float4*)W_IH);
    k_gemm<<<dim3(16, 256), 256, NSTAGE * STAGE_BYTES>>>();
    k_scan<<<256, 256>>>(HH);
    k_ogemm<<<dim3(8, 4, 8), 256>>>(W_HO);
    k_reduce<<<256, 256>>>(b_HO, Y);
}

// round 5
// speedup vs baseline: 1.1112x; 1.0750x over previous
#include <cuda_runtime.h>
#include <cuda_fp16.h>
#include <cstdint>
#include <cstddef>

// ---------------------------------------------------------------------------
// Problem dims
// ---------------------------------------------------------------------------
#define T_DIM 256
#define B_DIM 128
#define I_DIM 512
#define H_DIM 2048
#define O_DIM 512
#define M_DIM (T_DIM * B_DIM)   // 32768 rows of proj

// ---------------------------------------------------------------------------
// Scratch (device globals)
// ---------------------------------------------------------------------------
__device__ __half g_Xh[(size_t)M_DIM * I_DIM];        // 33.5 MB fp16
__device__ __half g_Wh[(size_t)H_DIM * I_DIM];        // 2 MB fp16
__device__ __half g_proj[(size_t)M_DIM * H_DIM];      // 134 MB fp16
__device__ float  g_hfin[(size_t)B_DIM * H_DIM];      // 1 MB
__device__ float  g_part[8 * (size_t)B_DIM * O_DIM];  // 2 MB

// ---------------------------------------------------------------------------
// PTX helpers (Ampere-compatible: cp.async / ldmatrix / mma.sync)
// ---------------------------------------------------------------------------
__device__ __forceinline__ uint32_t smem_u32(const void* p) {
    uint32_t a;
    asm("{ .reg .u64 t; cvta.to.shared.u64 t, %1; cvt.u32.u64 %0, t; }" : "=r"(a) : "l"(p));
    return a;
}
__device__ __forceinline__ void cp16(uint32_t dst, const void* src) {
    asm volatile("cp.async.cg.shared.global [%0], [%1], 16;" :: "r"(dst), "l"(src));
}
#define CP_COMMIT() asm volatile("cp.async.commit_group;" ::: "memory")
#define CP_WAIT(n)  asm volatile("cp.async.wait_group %0;" :: "n"(n) : "memory")

__device__ __forceinline__ void ldm_x4(uint32_t* r, uint32_t addr) {
    asm volatile("ldmatrix.sync.aligned.m8n8.x4.shared.b16 {%0,%1,%2,%3}, [%4];"
                 : "=r"(r[0]), "=r"(r[1]), "=r"(r[2]), "=r"(r[3]) : "r"(addr));
}
__device__ __forceinline__ void mma16816(float* c, const uint32_t* a, uint32_t b0, uint32_t b1) {
    asm volatile(
        "mma.sync.aligned.m16n8k16.row.col.f32.f16.f16.f32 "
        "{%0,%1,%2,%3}, {%4,%5,%6,%7}, {%8,%9}, {%0,%1,%2,%3};"
        : "+f"(c[0]), "+f"(c[1]), "+f"(c[2]), "+f"(c[3])
        : "r"(a[0]), "r"(a[1]), "r"(a[2]), "r"(a[3]), "r"(b0), "r"(b1));
}

// ---------------------------------------------------------------------------
// 1) fp32 -> fp16 conversion
// ---------------------------------------------------------------------------
__global__ void k_cvt_x(const float4* __restrict__ src, size_t base) {
    size_t i = base + (size_t)blockIdx.x * blockDim.x + threadIdx.x;
    float4 v = src[i];
    __half2 h0 = __floats2half2_rn(v.x, v.y);
    __half2 h1 = __floats2half2_rn(v.z, v.w);
    ((__half2*)g_Xh)[i * 2]     = h0;
    ((__half2*)g_Xh)[i * 2 + 1] = h1;
}
__global__ void k_cvt_w(const float4* __restrict__ src) {
    size_t i = (size_t)blockIdx.x * blockDim.x + threadIdx.x;  // 262,144
    float4 v = src[i];
    __half2 h0 = __floats2half2_rn(v.x, v.y);
    __half2 h1 = __floats2half2_rn(v.z, v.w);
    ((__half2*)g_Wh)[i * 2]     = h0;
    ((__half2*)g_Wh)[i * 2 + 1] = h1;
}

// ---------------------------------------------------------------------------
// 2) proj = X @ W_IH^T  (fp16 in, fp32 accum, fp16 out)
//    128x128x64 CTA tile, 4 warps (2x2), warp tile 64x64.
//    3-stage cp.async pipeline, one sync per k-tile, frag double-buffering.
// ---------------------------------------------------------------------------
#define STAGE_BYTES 32768          // A 16KB + B 16KB
#define NSTAGE 3

__global__ void __launch_bounds__(128, 2) k_gemm() {
    extern __shared__ __align__(1024) uint8_t dynsmem[];
    const uint32_t sbase = smem_u32(dynsmem);

    const int tid  = threadIdx.x;
    const int wid  = tid >> 5;
    const int lane = tid & 31;
    const int wm   = wid & 1;          // 0..1  (M direction)
    const int wn   = wid >> 1;         // 0..1  (N direction)
    const int n0   = blockIdx.x * 128; // over H
    const int m0   = blockIdx.y * 128; // over T*B

    const uint8_t* Ag = (const uint8_t*)(g_Xh + (size_t)m0 * I_DIM);
    const uint8_t* Bg = (const uint8_t*)(g_Wh + (size_t)n0 * I_DIM);

    float acc[4][8][4];
    #pragma unroll
    for (int i = 0; i < 4; ++i)
        #pragma unroll
        for (int j = 0; j < 8; ++j)
            #pragma unroll
            for (int q = 0; q < 4; ++q) acc[i][j][q] = 0.f;

    auto load_stage = [&](int kt, int st) {
        const uint32_t sA = sbase + st * STAGE_BYTES;
        const uint32_t sB = sA + 16384;
        const int koff = kt * 128;   // bytes along K
        #pragma unroll
        for (int i = 0; i < 8; ++i) {
            int c = tid + i * 128;           // 0..1023
            int row = c >> 3, j = c & 7;
            uint32_t sw = (uint32_t)(row * 128 + ((j ^ (row & 7)) * 16));
            cp16(sA + sw, Ag + (size_t)row * 1024 + koff + j * 16);
            cp16(sB + sw, Bg + (size_t)row * 1024 + koff + j * 16);
        }
    };

    // fragment double buffers: 64x64 warp tile
    uint32_t a_frag[2][4][4];
    uint32_t b_frag[2][4][4];
    const int rA0 = wm * 64 + (lane & 15);
    const int rB0 = wn * 64 + (lane & 15);
    const int jlo = (lane >> 4);

    auto ld_frags = [&](int buf, uint32_t sA, uint32_t sB, int ks) {
        const int j = ks * 2 + jlo;
        #pragma unroll
        for (int im = 0; im < 4; ++im) {
            int r = rA0 + im * 16;
            ldm_x4(a_frag[buf][im], sA + r * 128 + ((j ^ (r & 7)) * 16));
        }
        #pragma unroll
        for (int in = 0; in < 4; ++in) {
            int r = rB0 + in * 16;
            ldm_x4(b_frag[buf][in], sB + r * 128 + ((j ^ (r & 7)) * 16));
        }
    };

    // prologue
    load_stage(0, 0); CP_COMMIT();
    load_stage(1, 1); CP_COMMIT();
    CP_WAIT(1);
    __syncthreads();
    ld_frags(0, sbase, sbase + 16384, 0);

    for (int kt = 0; kt < 8; ++kt) {
        const uint32_t sA  = sbase + (kt % NSTAGE) * STAGE_BYTES;
        const uint32_t sB  = sA + 16384;
        const uint32_t sAn = sbase + ((kt + 1) % NSTAGE) * STAGE_BYTES;
        const uint32_t sBn = sAn + 16384;

        #pragma unroll
        for (int ks = 0; ks < 4; ++ks) {
            const int cur = ks & 1, nxt = cur ^ 1;
            if (ks == 0) {
                if (kt + 2 < 8) load_stage(kt + 2, (kt + 2) % NSTAGE);
                CP_COMMIT();
            }
            if (ks == 3) {
                CP_WAIT(1);
                __syncthreads();
                ld_frags(nxt, sAn, sBn, 0);     // first frags of next stage
            } else {
                ld_frags(nxt, sA, sB, ks + 1);
            }
            #pragma unroll
            for (int im = 0; im < 4; ++im)
                #pragma unroll
                for (int in = 0; in < 4; ++in) {
                    mma16816(acc[im][2 * in + 0], a_frag[cur][im],
                             b_frag[cur][in][0], b_frag[cur][in][2]);
                    mma16816(acc[im][2 * in + 1], a_frag[cur][im],
                             b_frag[cur][in][1], b_frag[cur][in][3]);
                }
        }
    }

    // epilogue: fp32 acc -> fp16 proj
    #pragma unroll
    for (int im = 0; im < 4; ++im) {
        const int rbase = m0 + wm * 64 + im * 16 + (lane >> 2);
        #pragma unroll
        for (int jn = 0; jn < 8; ++jn) {
            const int col = n0 + wn * 64 + jn * 8 + (lane & 3) * 2;
            __half2 v0 = __floats2half2_rn(acc[im][jn][0], acc[im][jn][1]);
            __half2 v1 = __floats2half2_rn(acc[im][jn][2], acc[im][jn][3]);
            *(__half2*)(g_proj + (size_t)rbase * H_DIM + col)       = v0;
            *(__half2*)(g_proj + (size_t)(rbase + 8) * H_DIM + col) = v1;
        }
    }
}

// ---------------------------------------------------------------------------
// 3) scan over t:  h = |proj_t + HH*h|
// ---------------------------------------------------------------------------
__global__ void __launch_bounds__(256) k_scan(const float* __restrict__ HH) {
    const int idx = blockIdx.x * blockDim.x + threadIdx.x;  // 65536 = B*H/4
    const int h4 = idx & (H_DIM / 4 - 1);
    const int b  = idx >> 9;
    const int h  = h4 * 4;
    const float hh0 = HH[h], hh1 = HH[h + 1], hh2 = HH[h + 2], hh3 = HH[h + 3];
    const uint2* p = (const uint2*)g_proj + ((size_t)b * H_DIM + h) / 4;
    const size_t tstride = (size_t)B_DIM * H_DIM / 4;   // in uint2
    float a0 = 0.f, a1 = 0.f, a2 = 0.f, a3 = 0.f;
    #pragma unroll 8
    for (int t = 0; t < T_DIM; ++t) {
        uint2 u = p[(size_t)t * tstride];
        __half2 lo = *(__half2*)&u.x;
        __half2 hi = *(__half2*)&u.y;
        float2 f0 = __half22float2(lo);
        float2 f1 = __half22float2(hi);
        a0 = fabsf(f0.x + hh0 * a0);
        a1 = fabsf(f0.y + hh1 * a1);
        a2 = fabsf(f1.x + hh2 * a2);
        a3 = fabsf(f1.y + hh3 * a3);
    }
    float4* out = (float4*)(g_hfin + (size_t)b * H_DIM + h);
    *out = make_float4(a0, a1, a2, a3);
}

// ---------------------------------------------------------------------------
// 4) Y = h @ W_HO^T + b : 8-way K-split partial GEMM + reduction
// ---------------------------------------------------------------------------
__global__ void k_ogemm(const float* __restrict__ W) {
    __shared__ float hs[32][65];
    __shared__ float ws[64][65];
    const int tid = threadIdx.x;
    const int tx = tid & 63;
    const int ty = tid >> 6;
    const int o0 = blockIdx.x * 64;
    const int b0 = blockIdx.y * 32;
    const int kb = blockIdx.z * 256;

    float acc[8];
    #pragma unroll
    for (int j = 0; j < 8; ++j) acc[j] = 0.f;

    for (int kc = 0; kc < 4; ++kc) {
        const int k0 = kb + kc * 64;
        #pragma unroll
        for (int l = 0; l < 8; ++l) {
            int i = tid + l * 256;
            int r = i >> 6, c = i & 63;
            hs[r][c] = g_hfin[(size_t)(b0 + r) * H_DIM + k0 + c];
        }
        #pragma unroll
        for (int l = 0; l < 16; ++l) {
            int i = tid + l * 256;
            int r = i >> 6, c = i & 63;
            ws[r][c] = W[(size_t)(o0 + r) * H_DIM + k0 + c];
        }
        __syncthreads();
        #pragma unroll
        for (int k = 0; k < 64; ++k) {
            float wv = ws[tx][k];
            #pragma unroll
            for (int j = 0; j < 8; ++j)
                acc[j] = fmaf(hs[ty + 4 * j][k], wv, acc[j]);
        }
        __syncthreads();
    }

    float* part = g_part + (size_t)blockIdx.z * (B_DIM * O_DIM);
    #pragma unroll
    for (int j = 0; j < 8; ++j)
        part[(size_t)(b0 + ty + 4 * j) * O_DIM + o0 + tx] = acc[j];
}

__global__ void k_reduce(const float* __restrict__ bias, float* __restrict__ Y) {
    const int i = blockIdx.x * blockDim.x + threadIdx.x;  // 65536
    float s = bias[i & (O_DIM - 1)];
    #pragma unroll
    for (int p = 0; p < 8; ++p) s += g_part[(size_t)p * (B_DIM * O_DIM) + i];
    Y[i] = s;
}

// ---------------------------------------------------------------------------
// launch
// ---------------------------------------------------------------------------
extern "C" void kernel_launch(void* const* d_in, const int* in_sizes, int n_in,
                              void* d_out, int out_size) {
    const float* X    = (const float*)d_in[0];
    const float* W_IH = (const float*)d_in[1];
    const float* HH   = (const float*)d_in[2];
    const float* W_HO = (const float*)d_in[3];
    const float* b_HO = (const float*)d_in[4];
    float* Y = (float*)d_out;

    cudaFuncSetAttribute(k_gemm, cudaFuncAttributeMaxDynamicSharedMemorySize,
                         NSTAGE * STAGE_BYTES);

    // keep k_gemm at launch #4 (ncu capture slot)
    k_cvt_x<<<8192, 256>>>((const float4*)X, 0);
    k_cvt_x<<<8192, 256>>>((const float4*)X, (size_t)8192 * 256);
    k_cvt_w<<<1024, 256>>>((const float4*)W_IH);
    k_gemm<<<dim3(16, 256), 128, NSTAGE * STAGE_BYTES>>>();
    k_scan<<<256, 256>>>(HH);
    k_ogemm<<<dim3(8, 4, 8), 256>>>(W_HO);
    k_reduce<<<256, 256>>>(b_HO, Y);
}